// round 11
// baseline (speedup 1.0000x reference)
#include <cuda_runtime.h>
#include <cfloat>

// Problem constants
#define BBATCH 1024
#define NA     16     // agents n
#define MI     16     // items m
#define MENU   256
#define KTOT   257    // MENU + null option
#define NM     256    // NA*MI
#define NM4    64     // NM/4
#define PAWS   17     // padded row stride for per-agent-welfare

// Output layout: concatenation of the reference's 6 returned arrays (all f32)
#define OFF_CHOICE 0                                    // [B,KTOT]
#define OFF_ITEM   (OFF_CHOICE + (size_t)BBATCH*KTOT)   // [B,NA,MI]
#define OFF_UTIL   (OFF_ITEM   + (size_t)BBATCH*NM)     // [NA,B]
#define OFF_PAY    (OFF_UTIL   + (size_t)NA*BBATCH)     // [NA,B]
#define OFF_ALLOCP (OFF_PAY    + (size_t)NA*BBATCH)     // [B,KTOT,NA,MI]
#define OFF_BREV   (OFF_ALLOCP + (size_t)BBATCH*KTOT*NM)// [NA,B]

__device__ __forceinline__ float dot4(float4 a, float4 b) {
    return a.x * b.x + a.y * b.y + a.z * b.z + a.w * b.w;
}

__global__ __launch_bounds__(256, 4)
void ramanet_kernel(const float* __restrict__ bids,
                    const float* __restrict__ values,
                    const float* __restrict__ allocs,
                    const float* __restrict__ wv,
                    const float* __restrict__ bv,
                    const int*   __restrict__ temp_ptr,
                    float* __restrict__ out)
{
    const int b    = blockIdx.x;
    const int tid  = threadIdx.x;
    const int warp = tid >> 5;
    const int lane = tid & 31;

    // decode softmax_temp robustly (int32 500 or float32 500.0f bit pattern)
    int ti = *temp_ptr;
    const float temp = (ti >= 1 && ti <= 10000000) ? (float)ti : __int_as_float(ti);

    __shared__ float4 wvb4_s[NM4];           // w[n] * (value - bid), as float4
    __shared__ float  w_s[NA];
    __shared__ float  bp_s[KTOT];
    __shared__ float  paw_s[KTOT * PAWS];
    __shared__ float  tw_s[KTOT];
    __shared__ float  choice_s[KTOT];
    __shared__ float  item_s[NM];
    __shared__ float  red_s[8];
    __shared__ float  red3_s[24];
    __shared__ float  bc_s[4];               // invSum, chosen_sum, alloc_b, maxv
    __shared__ float  rcs_s[NA], rb_s[NA];

    // ---- stage small per-batch data ----
    {
        size_t base = (size_t)b * NM;
        if (tid < NA) w_s[tid] = wv[(size_t)b * NA + tid];
        item_s[tid] = 0.f;
        bp_s[tid]   = bv[(size_t)b * MENU + tid];
        if (tid == 0) bp_s[MENU] = 0.f;
        __syncthreads();   // w_s ready before folding into wvb
        float vb = values[base + tid] - bids[base + tid];
        ((float*)wvb4_s)[tid] = vb * w_s[tid >> 4];   // fold w[n] in (n = tid/16)
    }
    __syncthreads();

    // ---- SINGLE PASS over allocs, x4-k burst per warp (8 LDG.128 = 1KB in
    //      flight per warp): copy-out + per_agent_welfare + total_welfare +
    //      online-softmax accumulation of item_allocation ----
    const float4* abase4 = (const float4*)(allocs + (size_t)b * MENU * NM);
    float4*       outP4  = (float4*)(out + OFF_ALLOCP + (size_t)b * KTOT * NM);

    float  Mw = -FLT_MAX;                         // per-warp running max
    float4 A0 = make_float4(0.f, 0.f, 0.f, 0.f);  // Σ e^{l-Mw} * allocs
    float4 A1 = make_float4(0.f, 0.f, 0.f, 0.f);

    // wvb kept addressable in smem so ptxas can re-load instead of spilling
    const float4* wvb0p = &wvb4_s[lane];          // agent n = lane/4
    const float4* wvb1p = &wvb4_s[32 + lane];     // agent n = 8 + lane/4

    for (int k = warp; k < MENU; k += 32) {
        // ---- 8 independent LDG.128 back-to-back (1KB in flight) ----
        float4 t0[4], t1[4];
        #pragma unroll
        for (int j = 0; j < 4; ++j) {
            const float4* p = abase4 + (size_t)(k + 8 * j) * NM4;
            t0[j] = __ldcs(&p[lane]);
            t1[j] = __ldcs(&p[32 + lane]);
        }
        // ---- 8 STG.128 copy-out ----
        #pragma unroll
        for (int j = 0; j < 4; ++j) {
            float4* q = outP4 + (size_t)(k + 8 * j) * NM4;
            __stcs(&q[lane],      t0[j]);
            __stcs(&q[32 + lane], t1[j]);
        }

        // ---- weighted partial dots ----
        const float4 wvb0 = *wvb0p;
        const float4 wvb1 = *wvb1p;
        float d0[4], d1[4];
        #pragma unroll
        for (int j = 0; j < 4; ++j) {
            d0[j] = dot4(t0[j], wvb0);
            d1[j] = dot4(t1[j], wvb1);
        }
        // butterfly over the 4 lanes of each agent group
        #pragma unroll
        for (int j = 0; j < 4; ++j) {
            d0[j] += __shfl_xor_sync(0xffffffffu, d0[j], 2);
            d1[j] += __shfl_xor_sync(0xffffffffu, d1[j], 2);
            d0[j] += __shfl_xor_sync(0xffffffffu, d0[j], 1);
            d1[j] += __shfl_xor_sync(0xffffffffu, d1[j], 1);
        }
        if ((lane & 3) == 0) {
            int n0 = lane >> 2;
            #pragma unroll
            for (int j = 0; j < 4; ++j) {
                paw_s[(k + 8 * j) * PAWS + n0]     = d0[j];
                paw_s[(k + 8 * j) * PAWS + 8 + n0] = d1[j];
            }
        }
        // total welfare: butterfly over the 8 agent groups
        float s[4];
        #pragma unroll
        for (int j = 0; j < 4; ++j) {
            s[j] = d0[j] + d1[j];
            s[j] += __shfl_xor_sync(0xffffffffu, s[j], 4);
            s[j] += __shfl_xor_sync(0xffffffffu, s[j], 8);
            s[j] += __shfl_xor_sync(0xffffffffu, s[j], 16);
        }
        if (lane == 0) {
            #pragma unroll
            for (int j = 0; j < 4; ++j) tw_s[k + 8 * j] = s[j];
        }

        // combined online-softmax update for 4 k's (one rescale, 5 exps)
        float l[4];
        #pragma unroll
        for (int j = 0; j < 4; ++j) l[j] = (s[j] + bp_s[k + 8 * j]) * temp;
        float Mn = fmaxf(fmaxf(Mw, fmaxf(l[0], l[1])), fmaxf(l[2], l[3]));
        float sc = __expf(Mw - Mn);
        Mw = Mn;
        A0.x *= sc; A0.y *= sc; A0.z *= sc; A0.w *= sc;
        A1.x *= sc; A1.y *= sc; A1.z *= sc; A1.w *= sc;
        #pragma unroll
        for (int j = 0; j < 4; ++j) {
            float c = __expf(l[j] - Mn);
            A0.x += c * t0[j].x;  A0.y += c * t0[j].y;
            A0.z += c * t0[j].z;  A0.w += c * t0[j].w;
            A1.x += c * t1[j].x;  A1.y += c * t1[j].y;
            A1.z += c * t1[j].z;  A1.w += c * t1[j].w;
        }
    }

    // null allocation row = zeros (64 float4)
    if (tid < 64)
        __stcs(&((float4*)((float*)outP4 + (size_t)MENU * NM))[tid],
               make_float4(0.f, 0.f, 0.f, 0.f));
    if (tid < NA) paw_s[MENU * PAWS + tid] = 0.f;   // null option
    if (tid == 0) tw_s[MENU] = 0.f;
    __syncthreads();

    // ---- main softmax over K=257 logits = (tw + bp)*temp ----
    float l0 = (tw_s[tid] + bp_s[tid]) * temp;       // k = tid
    {
        float mx = l0;
        if (tid == 0) mx = fmaxf(mx, 0.f);           // k=256 null logit = 0
        #pragma unroll
        for (int o = 16; o; o >>= 1) mx = fmaxf(mx, __shfl_xor_sync(0xffffffffu, mx, o));
        if (lane == 0) red_s[warp] = mx;
        __syncthreads();
        if (warp == 0) {
            float v = (lane < 8) ? red_s[lane] : -3.4e38f;
            #pragma unroll
            for (int o = 4; o; o >>= 1) v = fmaxf(v, __shfl_xor_sync(0xffffffffu, v, o));
            if (lane == 0) bc_s[3] = v;
        }
        __syncthreads();
    }
    const float maxv = bc_s[3];
    float e0 = __expf(l0 - maxv);
    choice_s[tid] = e0;
    float eNull = 0.f;
    if (tid == 0) { eNull = __expf(0.f - maxv); choice_s[MENU] = eNull; }

    // triple block sum: (Σe, Σe*tw, Σe*bp)
    {
        float s0 = e0 + eNull;                       // null adds e; its tw=bp=0
        float s1 = e0 * tw_s[tid];
        float s2 = e0 * bp_s[tid];
        #pragma unroll
        for (int o = 16; o; o >>= 1) {
            s0 += __shfl_xor_sync(0xffffffffu, s0, o);
            s1 += __shfl_xor_sync(0xffffffffu, s1, o);
            s2 += __shfl_xor_sync(0xffffffffu, s2, o);
        }
        if (lane == 0) { red3_s[warp] = s0; red3_s[8+warp] = s1; red3_s[16+warp] = s2; }
        __syncthreads();
        if (warp == 0) {
            float a = (lane < 8) ? red3_s[lane]     : 0.f;
            float c = (lane < 8) ? red3_s[8+lane]   : 0.f;
            float d = (lane < 8) ? red3_s[16+lane]  : 0.f;
            #pragma unroll
            for (int o = 4; o; o >>= 1) {
                a += __shfl_xor_sync(0xffffffffu, a, o);
                c += __shfl_xor_sync(0xffffffffu, c, o);
                d += __shfl_xor_sync(0xffffffffu, d, o);
            }
            if (lane == 0) {
                float inv = 1.f / a;
                bc_s[0] = inv;
                bc_s[1] = c * inv;   // chosen_sum
                bc_s[2] = d * inv;   // alloc_b
            }
        }
        __syncthreads();
    }
    const float invSum = bc_s[0];
    // write alloc_choice
    out[OFF_CHOICE + (size_t)b * KTOT + tid] = choice_s[tid] * invSum;
    if (tid == 0)
        out[OFF_CHOICE + (size_t)b * KTOT + MENU] = choice_s[MENU] * invSum;

    // ---- merge per-warp online accumulators into item_allocation ----
    {
        float r = __expf(Mw - maxv) * invSum;        // lane-uniform per warp
        int base0 = lane * 4, base1 = (32 + lane) * 4;
        atomicAdd(&item_s[base0 + 0], A0.x * r);
        atomicAdd(&item_s[base0 + 1], A0.y * r);
        atomicAdd(&item_s[base0 + 2], A0.z * r);
        atomicAdd(&item_s[base0 + 3], A0.w * r);
        atomicAdd(&item_s[base1 + 0], A1.x * r);
        atomicAdd(&item_s[base1 + 1], A1.y * r);
        atomicAdd(&item_s[base1 + 2], A1.z * r);
        atomicAdd(&item_s[base1 + 3], A1.w * r);
    }

    // ---- counterfactual softmaxes: warp handles agents i = warp, warp+8 ----
    for (int i = warp; i < NA; i += 8) {
        float mx = -3.4e38f;
        for (int kk = lane; kk < KTOT; kk += 32) {
            float l = (tw_s[kk] - paw_s[kk * PAWS + i] + bp_s[kk]) * temp;
            mx = fmaxf(mx, l);
        }
        #pragma unroll
        for (int o = 16; o; o >>= 1) mx = fmaxf(mx, __shfl_xor_sync(0xffffffffu, mx, o));
        float s0 = 0.f, s1 = 0.f, s2 = 0.f;
        for (int kk = lane; kk < KTOT; kk += 32) {
            float trm = tw_s[kk] - paw_s[kk * PAWS + i];
            float bp  = bp_s[kk];
            float e   = __expf((trm + bp) * temp - mx);
            s0 += e; s1 += e * trm; s2 += e * bp;
        }
        #pragma unroll
        for (int o = 16; o; o >>= 1) {
            s0 += __shfl_xor_sync(0xffffffffu, s0, o);
            s1 += __shfl_xor_sync(0xffffffffu, s1, o);
            s2 += __shfl_xor_sync(0xffffffffu, s2, o);
        }
        if (lane == 0) { rcs_s[i] = s1 / s0; rb_s[i] = s2 / s0; }
    }
    __syncthreads();   // item_s atomics + rcs/rb ready

    // ---- item_allocation out + payments / utility / bid_rev ----
    out[OFF_ITEM + (size_t)b * NM + tid] = item_s[tid];
    if (tid < NA) {
        float br = 0.f, val = 0.f;
        size_t base = (size_t)b * NM + (size_t)tid * MI;
        #pragma unroll
        for (int m = 0; m < MI; ++m) {
            float it = item_s[tid * MI + m];
            br  += it * bids[base + m];
            val += it * values[base + m];
        }
        float pay = (bc_s[1] + bc_s[2] - rcs_s[tid] - rb_s[tid]) / w_s[tid] + br;
        out[OFF_UTIL + (size_t)tid * BBATCH + b] = val - pay;
        out[OFF_PAY  + (size_t)tid * BBATCH + b] = pay;
        out[OFF_BREV + (size_t)tid * BBATCH + b] = br;
    }
}

extern "C" void kernel_launch(void* const* d_in, const int* in_sizes, int n_in,
                              void* d_out, int out_size)
{
    const float* bids   = (const float*)d_in[0];
    const float* values = (const float*)d_in[1];
    const float* allocs = (const float*)d_in[2];
    const float* w      = (const float*)d_in[3];
    const float* b      = (const float*)d_in[4];
    const int*   temp   = (const int*)  d_in[5];
    float* out = (float*)d_out;

    ramanet_kernel<<<BBATCH, 256>>>(bids, values, allocs, w, b, temp, out);
}

// round 12
// speedup vs baseline: 1.0405x; 1.0405x over previous
#include <cuda_runtime.h>
#include <cfloat>

// Problem constants
#define BBATCH 1024
#define NA     16     // agents n
#define MI     16     // items m
#define MENU   256
#define KTOT   257    // MENU + null option
#define NM     256    // NA*MI
#define NM4    64     // NM/4
#define PAWS   17     // padded row stride for per-agent-welfare

// Output layout: concatenation of the reference's 6 returned arrays (all f32)
#define OFF_CHOICE 0                                    // [B,KTOT]
#define OFF_ITEM   (OFF_CHOICE + (size_t)BBATCH*KTOT)   // [B,NA,MI]
#define OFF_UTIL   (OFF_ITEM   + (size_t)BBATCH*NM)     // [NA,B]
#define OFF_PAY    (OFF_UTIL   + (size_t)NA*BBATCH)     // [NA,B]
#define OFF_ALLOCP (OFF_PAY    + (size_t)NA*BBATCH)     // [B,KTOT,NA,MI]
#define OFF_BREV   (OFF_ALLOCP + (size_t)BBATCH*KTOT*NM)// [NA,B]

__device__ __forceinline__ float dot4(float4 a, float4 b) {
    return a.x * b.x + a.y * b.y + a.z * b.z + a.w * b.w;
}

__global__ __launch_bounds__(256, 4)
void ramanet_kernel(const float* __restrict__ bids,
                    const float* __restrict__ values,
                    const float* __restrict__ allocs,
                    const float* __restrict__ wv,
                    const float* __restrict__ bv,
                    const int*   __restrict__ temp_ptr,
                    float* __restrict__ out)
{
    const int b    = blockIdx.x;
    const int tid  = threadIdx.x;
    const int warp = tid >> 5;
    const int lane = tid & 31;

    // decode softmax_temp robustly (int32 500 or float32 500.0f bit pattern)
    int ti = *temp_ptr;
    const float temp = (ti >= 1 && ti <= 10000000) ? (float)ti : __int_as_float(ti);

    __shared__ float4 wvb4_s[NM4];           // w[n] * (value - bid), as float4
    __shared__ float  w_s[NA];
    __shared__ float  bp_s[KTOT];
    __shared__ float  paw_s[KTOT * PAWS];
    __shared__ float  tw_s[KTOT];
    __shared__ float  choice_s[KTOT];
    __shared__ float  item_s[NM];
    __shared__ float  red_s[8];
    __shared__ float  red3_s[24];
    __shared__ float  bc_s[4];               // invSum, chosen_sum, alloc_b, maxv
    __shared__ float  rcs_s[NA], rb_s[NA];

    // ---- stage small per-batch data ----
    {
        size_t base = (size_t)b * NM;
        if (tid < NA) w_s[tid] = wv[(size_t)b * NA + tid];
        item_s[tid] = 0.f;
        bp_s[tid]   = bv[(size_t)b * MENU + tid];
        if (tid == 0) bp_s[MENU] = 0.f;
        __syncthreads();   // w_s ready before folding into wvb
        float vb = values[base + tid] - bids[base + tid];
        ((float*)wvb4_s)[tid] = vb * w_s[tid >> 4];   // fold w[n] in (n = tid/16)
    }
    __syncthreads();

    // ---- SINGLE PASS over allocs (x2 per warp): copy-out + per_agent_welfare
    //      + total_welfare + online-softmax accumulation of item_allocation.
    //      A/B vs R5: stores use DEFAULT policy (write-back) instead of .cs ----
    const float4* abase4 = (const float4*)(allocs + (size_t)b * MENU * NM);
    float4*       outP4  = (float4*)(out + OFF_ALLOCP + (size_t)b * KTOT * NM);

    float  Mw = -FLT_MAX;                         // per-warp running max
    float4 A0 = make_float4(0.f, 0.f, 0.f, 0.f);  // Σ e^{l-Mw} * allocs
    float4 A1 = make_float4(0.f, 0.f, 0.f, 0.f);

    const float4 wvb0 = wvb4_s[lane];             // agent n = lane/4
    const float4 wvb1 = wvb4_s[32 + lane];        // agent n = 8 + lane/4

    for (int k = warp; k < MENU; k += 16) {
        const float4* pa = abase4 + (size_t)k * NM4;
        const float4* pb = pa + 8 * NM4;
        float4 va0 = __ldcs(&pa[lane]);
        float4 va1 = __ldcs(&pa[32 + lane]);
        float4 vc0 = __ldcs(&pb[lane]);
        float4 vc1 = __ldcs(&pb[32 + lane]);
        float4* qa = outP4 + (size_t)k * NM4;
        float4* qb = qa + 8 * NM4;
        qa[lane]      = va0;           // default STG.128 (write-back)
        qa[32 + lane] = va1;
        qb[lane]      = vc0;
        qb[32 + lane] = vc1;

        float ta0 = dot4(va0, wvb0);
        float ta1 = dot4(va1, wvb1);
        float tb0 = dot4(vc0, wvb0);
        float tb1 = dot4(vc1, wvb1);
        ta0 += __shfl_xor_sync(0xffffffffu, ta0, 2);
        ta1 += __shfl_xor_sync(0xffffffffu, ta1, 2);
        tb0 += __shfl_xor_sync(0xffffffffu, tb0, 2);
        tb1 += __shfl_xor_sync(0xffffffffu, tb1, 2);
        ta0 += __shfl_xor_sync(0xffffffffu, ta0, 1);
        ta1 += __shfl_xor_sync(0xffffffffu, ta1, 1);
        tb0 += __shfl_xor_sync(0xffffffffu, tb0, 1);
        tb1 += __shfl_xor_sync(0xffffffffu, tb1, 1);
        if ((lane & 3) == 0) {
            int n0 = lane >> 2;
            paw_s[k * PAWS + n0]            = ta0;
            paw_s[k * PAWS + 8 + n0]        = ta1;
            paw_s[(k + 8) * PAWS + n0]      = tb0;
            paw_s[(k + 8) * PAWS + 8 + n0]  = tb1;
        }
        float sa = ta0 + ta1;
        float sb = tb0 + tb1;
        sa += __shfl_xor_sync(0xffffffffu, sa, 4);
        sb += __shfl_xor_sync(0xffffffffu, sb, 4);
        sa += __shfl_xor_sync(0xffffffffu, sa, 8);
        sb += __shfl_xor_sync(0xffffffffu, sb, 8);
        sa += __shfl_xor_sync(0xffffffffu, sa, 16);
        sb += __shfl_xor_sync(0xffffffffu, sb, 16);
        if (lane == 0) { tw_s[k] = sa; tw_s[k + 8] = sb; }

        float la = (sa + bp_s[k]) * temp;
        float lb = (sb + bp_s[k + 8]) * temp;
        float Mn = fmaxf(Mw, fmaxf(la, lb));
        float sc = __expf(Mw - Mn);
        float ca = __expf(la - Mn);
        float cb = __expf(lb - Mn);
        Mw = Mn;
        A0.x = A0.x * sc + ca * va0.x + cb * vc0.x;
        A0.y = A0.y * sc + ca * va0.y + cb * vc0.y;
        A0.z = A0.z * sc + ca * va0.z + cb * vc0.z;
        A0.w = A0.w * sc + ca * va0.w + cb * vc0.w;
        A1.x = A1.x * sc + ca * va1.x + cb * vc1.x;
        A1.y = A1.y * sc + ca * va1.y + cb * vc1.y;
        A1.z = A1.z * sc + ca * va1.z + cb * vc1.z;
        A1.w = A1.w * sc + ca * va1.w + cb * vc1.w;
    }

    // null allocation row = zeros (64 float4)
    if (tid < 64)
        ((float4*)((float*)outP4 + (size_t)MENU * NM))[tid] =
            make_float4(0.f, 0.f, 0.f, 0.f);
    if (tid < NA) paw_s[MENU * PAWS + tid] = 0.f;   // null option
    if (tid == 0) tw_s[MENU] = 0.f;
    __syncthreads();

    // ---- main softmax over K=257 logits = (tw + bp)*temp ----
    float l0 = (tw_s[tid] + bp_s[tid]) * temp;       // k = tid
    {
        float mx = l0;
        if (tid == 0) mx = fmaxf(mx, 0.f);           // k=256 null logit = 0
        #pragma unroll
        for (int o = 16; o; o >>= 1) mx = fmaxf(mx, __shfl_xor_sync(0xffffffffu, mx, o));
        if (lane == 0) red_s[warp] = mx;
        __syncthreads();
        if (warp == 0) {
            float v = (lane < 8) ? red_s[lane] : -3.4e38f;
            #pragma unroll
            for (int o = 4; o; o >>= 1) v = fmaxf(v, __shfl_xor_sync(0xffffffffu, v, o));
            if (lane == 0) bc_s[3] = v;
        }
        __syncthreads();
    }
    const float maxv = bc_s[3];
    float e0 = __expf(l0 - maxv);
    choice_s[tid] = e0;
    float eNull = 0.f;
    if (tid == 0) { eNull = __expf(0.f - maxv); choice_s[MENU] = eNull; }

    // triple block sum: (Σe, Σe*tw, Σe*bp)
    {
        float s0 = e0 + eNull;                       // null adds e; its tw=bp=0
        float s1 = e0 * tw_s[tid];
        float s2 = e0 * bp_s[tid];
        #pragma unroll
        for (int o = 16; o; o >>= 1) {
            s0 += __shfl_xor_sync(0xffffffffu, s0, o);
            s1 += __shfl_xor_sync(0xffffffffu, s1, o);
            s2 += __shfl_xor_sync(0xffffffffu, s2, o);
        }
        if (lane == 0) { red3_s[warp] = s0; red3_s[8+warp] = s1; red3_s[16+warp] = s2; }
        __syncthreads();
        if (warp == 0) {
            float a = (lane < 8) ? red3_s[lane]     : 0.f;
            float c = (lane < 8) ? red3_s[8+lane]   : 0.f;
            float d = (lane < 8) ? red3_s[16+lane]  : 0.f;
            #pragma unroll
            for (int o = 4; o; o >>= 1) {
                a += __shfl_xor_sync(0xffffffffu, a, o);
                c += __shfl_xor_sync(0xffffffffu, c, o);
                d += __shfl_xor_sync(0xffffffffu, d, o);
            }
            if (lane == 0) {
                float inv = 1.f / a;
                bc_s[0] = inv;
                bc_s[1] = c * inv;   // chosen_sum
                bc_s[2] = d * inv;   // alloc_b
            }
        }
        __syncthreads();
    }
    const float invSum = bc_s[0];
    // write alloc_choice
    out[OFF_CHOICE + (size_t)b * KTOT + tid] = choice_s[tid] * invSum;
    if (tid == 0)
        out[OFF_CHOICE + (size_t)b * KTOT + MENU] = choice_s[MENU] * invSum;

    // ---- merge per-warp online accumulators into item_allocation ----
    {
        float r = __expf(Mw - maxv) * invSum;        // lane-uniform per warp
        int base0 = lane * 4, base1 = (32 + lane) * 4;
        atomicAdd(&item_s[base0 + 0], A0.x * r);
        atomicAdd(&item_s[base0 + 1], A0.y * r);
        atomicAdd(&item_s[base0 + 2], A0.z * r);
        atomicAdd(&item_s[base0 + 3], A0.w * r);
        atomicAdd(&item_s[base1 + 0], A1.x * r);
        atomicAdd(&item_s[base1 + 1], A1.y * r);
        atomicAdd(&item_s[base1 + 2], A1.z * r);
        atomicAdd(&item_s[base1 + 3], A1.w * r);
    }

    // ---- counterfactual softmaxes: warp handles agents i = warp, warp+8 ----
    for (int i = warp; i < NA; i += 8) {
        float mx = -3.4e38f;
        for (int kk = lane; kk < KTOT; kk += 32) {
            float l = (tw_s[kk] - paw_s[kk * PAWS + i] + bp_s[kk]) * temp;
            mx = fmaxf(mx, l);
        }
        #pragma unroll
        for (int o = 16; o; o >>= 1) mx = fmaxf(mx, __shfl_xor_sync(0xffffffffu, mx, o));
        float s0 = 0.f, s1 = 0.f, s2 = 0.f;
        for (int kk = lane; kk < KTOT; kk += 32) {
            float trm = tw_s[kk] - paw_s[kk * PAWS + i];
            float bp  = bp_s[kk];
            float e   = __expf((trm + bp) * temp - mx);
            s0 += e; s1 += e * trm; s2 += e * bp;
        }
        #pragma unroll
        for (int o = 16; o; o >>= 1) {
            s0 += __shfl_xor_sync(0xffffffffu, s0, o);
            s1 += __shfl_xor_sync(0xffffffffu, s1, o);
            s2 += __shfl_xor_sync(0xffffffffu, s2, o);
        }
        if (lane == 0) { rcs_s[i] = s1 / s0; rb_s[i] = s2 / s0; }
    }
    __syncthreads();   // item_s atomics + rcs/rb ready

    // ---- item_allocation out + payments / utility / bid_rev ----
    out[OFF_ITEM + (size_t)b * NM + tid] = item_s[tid];
    if (tid < NA) {
        float br = 0.f, val = 0.f;
        size_t base = (size_t)b * NM + (size_t)tid * MI;
        #pragma unroll
        for (int m = 0; m < MI; ++m) {
            float it = item_s[tid * MI + m];
            br  += it * bids[base + m];
            val += it * values[base + m];
        }
        float pay = (bc_s[1] + bc_s[2] - rcs_s[tid] - rb_s[tid]) / w_s[tid] + br;
        out[OFF_UTIL + (size_t)tid * BBATCH + b] = val - pay;
        out[OFF_PAY  + (size_t)tid * BBATCH + b] = pay;
        out[OFF_BREV + (size_t)tid * BBATCH + b] = br;
    }
}

extern "C" void kernel_launch(void* const* d_in, const int* in_sizes, int n_in,
                              void* d_out, int out_size)
{
    const float* bids   = (const float*)d_in[0];
    const float* values = (const float*)d_in[1];
    const float* allocs = (const float*)d_in[2];
    const float* w      = (const float*)d_in[3];
    const float* b      = (const float*)d_in[4];
    const int*   temp   = (const int*)  d_in[5];
    float* out = (float*)d_out;

    ramanet_kernel<<<BBATCH, 256>>>(bids, values, allocs, w, b, temp, out);
}

// round 13
// speedup vs baseline: 1.0665x; 1.0249x over previous
#include <cuda_runtime.h>
#include <cfloat>

// Problem constants
#define BBATCH 1024
#define NA     16     // agents n
#define MI     16     // items m
#define MENU   256
#define KTOT   257    // MENU + null option
#define NM     256    // NA*MI
#define NM4    64     // NM/4
#define PAWS   17     // padded row stride for per-agent-welfare

// Output layout: concatenation of the reference's 6 returned arrays (all f32)
#define OFF_CHOICE 0                                    // [B,KTOT]
#define OFF_ITEM   (OFF_CHOICE + (size_t)BBATCH*KTOT)   // [B,NA,MI]
#define OFF_UTIL   (OFF_ITEM   + (size_t)BBATCH*NM)     // [NA,B]
#define OFF_PAY    (OFF_UTIL   + (size_t)NA*BBATCH)     // [NA,B]
#define OFF_ALLOCP (OFF_PAY    + (size_t)NA*BBATCH)     // [B,KTOT,NA,MI]
#define OFF_BREV   (OFF_ALLOCP + (size_t)BBATCH*KTOT*NM)// [NA,B]

__device__ __forceinline__ float dot4(float4 a, float4 b) {
    return a.x * b.x + a.y * b.y + a.z * b.z + a.w * b.w;
}

__global__ __launch_bounds__(256, 4)
void ramanet_kernel(const float* __restrict__ bids,
                    const float* __restrict__ values,
                    const float* __restrict__ allocs,
                    const float* __restrict__ wv,
                    const float* __restrict__ bv,
                    const int*   __restrict__ temp_ptr,
                    float* __restrict__ out)
{
    const int b    = blockIdx.x;
    const int tid  = threadIdx.x;
    const int warp = tid >> 5;
    const int lane = tid & 31;

    // decode softmax_temp robustly (int32 500 or float32 500.0f bit pattern)
    int ti = *temp_ptr;
    const float temp = (ti >= 1 && ti <= 10000000) ? (float)ti : __int_as_float(ti);

    __shared__ float4 wvb4_s[NM4];           // w[n] * (value - bid), as float4
    __shared__ float  w_s[NA];
    __shared__ float  bp_s[KTOT];
    __shared__ float  paw_s[KTOT * PAWS];
    __shared__ float  tw_s[KTOT];
    __shared__ float  choice_s[KTOT];
    __shared__ float  item_s[NM];
    __shared__ float  red_s[8];
    __shared__ float  red3_s[24];
    __shared__ float  bc_s[4];               // invSum, chosen_sum, alloc_b, maxv
    __shared__ float  rcs_s[NA], rb_s[NA];

    const float4* abase4 = (const float4*)(allocs + (size_t)b * MENU * NM);
    float4*       outP4  = (float4*)(out + OFF_ALLOCP + (size_t)b * KTOT * NM);

    // null allocation row = zeros (64 float4) — issued early, off the tail
    if (tid < 64)
        __stcs(&((float4*)((float*)outP4 + (size_t)MENU * NM))[tid],
               make_float4(0.f, 0.f, 0.f, 0.f));

    // ---- stage small per-batch data ----
    {
        size_t base = (size_t)b * NM;
        if (tid < NA) w_s[tid] = wv[(size_t)b * NA + tid];
        item_s[tid] = 0.f;
        bp_s[tid]   = bv[(size_t)b * MENU + tid];
        if (tid == 0) bp_s[MENU] = 0.f;
        __syncthreads();   // w_s ready before folding into wvb
        float vb = values[base + tid] - bids[base + tid];
        ((float*)wvb4_s)[tid] = vb * w_s[tid >> 4];   // fold w[n] in (n = tid/16)
    }
    __syncthreads();

    // ---- SINGLE PASS over allocs (x2 per warp): copy-out + per_agent_welfare
    //      + total_welfare + online-softmax accumulation of item_allocation ----
    float  Mw = -FLT_MAX;                         // per-warp running max
    float4 A0 = make_float4(0.f, 0.f, 0.f, 0.f);  // Σ e^{l-Mw} * allocs
    float4 A1 = make_float4(0.f, 0.f, 0.f, 0.f);

    const float4 wvb0 = wvb4_s[lane];             // agent n = lane/4
    const float4 wvb1 = wvb4_s[32 + lane];        // agent n = 8 + lane/4

    for (int k = warp; k < MENU; k += 16) {
        const float4* pa = abase4 + (size_t)k * NM4;
        const float4* pb = pa + 8 * NM4;
        float4 va0 = __ldcs(&pa[lane]);
        float4 va1 = __ldcs(&pa[32 + lane]);
        float4 vc0 = __ldcs(&pb[lane]);
        float4 vc1 = __ldcs(&pb[32 + lane]);
        float4* qa = outP4 + (size_t)k * NM4;
        float4* qb = qa + 8 * NM4;
        __stcs(&qa[lane],      va0);
        __stcs(&qa[32 + lane], va1);
        __stcs(&qb[lane],      vc0);
        __stcs(&qb[32 + lane], vc1);

        float ta0 = dot4(va0, wvb0);
        float ta1 = dot4(va1, wvb1);
        float tb0 = dot4(vc0, wvb0);
        float tb1 = dot4(vc1, wvb1);
        ta0 += __shfl_xor_sync(0xffffffffu, ta0, 2);
        ta1 += __shfl_xor_sync(0xffffffffu, ta1, 2);
        tb0 += __shfl_xor_sync(0xffffffffu, tb0, 2);
        tb1 += __shfl_xor_sync(0xffffffffu, tb1, 2);
        ta0 += __shfl_xor_sync(0xffffffffu, ta0, 1);
        ta1 += __shfl_xor_sync(0xffffffffu, ta1, 1);
        tb0 += __shfl_xor_sync(0xffffffffu, tb0, 1);
        tb1 += __shfl_xor_sync(0xffffffffu, tb1, 1);
        if ((lane & 3) == 0) {
            int n0 = lane >> 2;
            paw_s[k * PAWS + n0]            = ta0;
            paw_s[k * PAWS + 8 + n0]        = ta1;
            paw_s[(k + 8) * PAWS + n0]      = tb0;
            paw_s[(k + 8) * PAWS + 8 + n0]  = tb1;
        }
        float sa = ta0 + ta1;
        float sb = tb0 + tb1;
        sa += __shfl_xor_sync(0xffffffffu, sa, 4);
        sb += __shfl_xor_sync(0xffffffffu, sb, 4);
        sa += __shfl_xor_sync(0xffffffffu, sa, 8);
        sb += __shfl_xor_sync(0xffffffffu, sb, 8);
        sa += __shfl_xor_sync(0xffffffffu, sa, 16);
        sb += __shfl_xor_sync(0xffffffffu, sb, 16);
        if (lane == 0) { tw_s[k] = sa; tw_s[k + 8] = sb; }

        float la = (sa + bp_s[k]) * temp;
        float lb = (sb + bp_s[k + 8]) * temp;
        float Mn = fmaxf(Mw, fmaxf(la, lb));
        float sc = __expf(Mw - Mn);
        float ca = __expf(la - Mn);
        float cb = __expf(lb - Mn);
        Mw = Mn;
        A0.x = A0.x * sc + ca * va0.x + cb * vc0.x;
        A0.y = A0.y * sc + ca * va0.y + cb * vc0.y;
        A0.z = A0.z * sc + ca * va0.z + cb * vc0.z;
        A0.w = A0.w * sc + ca * va0.w + cb * vc0.w;
        A1.x = A1.x * sc + ca * va1.x + cb * vc1.x;
        A1.y = A1.y * sc + ca * va1.y + cb * vc1.y;
        A1.z = A1.z * sc + ca * va1.z + cb * vc1.z;
        A1.w = A1.w * sc + ca * va1.w + cb * vc1.w;
    }

    if (tid < NA) paw_s[MENU * PAWS + tid] = 0.f;   // null option
    if (tid == 0) tw_s[MENU] = 0.f;
    __syncthreads();

    // ---- main softmax over K=257 logits = (tw + bp)*temp ----
    float l0 = (tw_s[tid] + bp_s[tid]) * temp;       // k = tid
    {
        float mx = l0;
        if (tid == 0) mx = fmaxf(mx, 0.f);           // k=256 null logit = 0
        #pragma unroll
        for (int o = 16; o; o >>= 1) mx = fmaxf(mx, __shfl_xor_sync(0xffffffffu, mx, o));
        if (lane == 0) red_s[warp] = mx;
        __syncthreads();
        if (warp == 0) {
            float v = (lane < 8) ? red_s[lane] : -3.4e38f;
            #pragma unroll
            for (int o = 4; o; o >>= 1) v = fmaxf(v, __shfl_xor_sync(0xffffffffu, v, o));
            if (lane == 0) bc_s[3] = v;
        }
        __syncthreads();
    }
    const float maxv = bc_s[3];
    float e0 = __expf(l0 - maxv);
    choice_s[tid] = e0;
    float eNull = 0.f;
    if (tid == 0) { eNull = __expf(0.f - maxv); choice_s[MENU] = eNull; }

    // triple block sum: (Σe, Σe*tw, Σe*bp)
    {
        float s0 = e0 + eNull;                       // null adds e; its tw=bp=0
        float s1 = e0 * tw_s[tid];
        float s2 = e0 * bp_s[tid];
        #pragma unroll
        for (int o = 16; o; o >>= 1) {
            s0 += __shfl_xor_sync(0xffffffffu, s0, o);
            s1 += __shfl_xor_sync(0xffffffffu, s1, o);
            s2 += __shfl_xor_sync(0xffffffffu, s2, o);
        }
        if (lane == 0) { red3_s[warp] = s0; red3_s[8+warp] = s1; red3_s[16+warp] = s2; }
        __syncthreads();
        if (warp == 0) {
            float a = (lane < 8) ? red3_s[lane]     : 0.f;
            float c = (lane < 8) ? red3_s[8+lane]   : 0.f;
            float d = (lane < 8) ? red3_s[16+lane]  : 0.f;
            #pragma unroll
            for (int o = 4; o; o >>= 1) {
                a += __shfl_xor_sync(0xffffffffu, a, o);
                c += __shfl_xor_sync(0xffffffffu, c, o);
                d += __shfl_xor_sync(0xffffffffu, d, o);
            }
            if (lane == 0) {
                float inv = 1.f / a;
                bc_s[0] = inv;
                bc_s[1] = c * inv;   // chosen_sum
                bc_s[2] = d * inv;   // alloc_b
            }
        }
        __syncthreads();
    }
    const float invSum = bc_s[0];
    // write alloc_choice
    out[OFF_CHOICE + (size_t)b * KTOT + tid] = choice_s[tid] * invSum;
    if (tid == 0)
        out[OFF_CHOICE + (size_t)b * KTOT + MENU] = choice_s[MENU] * invSum;

    // ---- merge per-warp online accumulators into item_allocation ----
    {
        float r = __expf(Mw - maxv) * invSum;        // lane-uniform per warp
        int base0 = lane * 4, base1 = (32 + lane) * 4;
        atomicAdd(&item_s[base0 + 0], A0.x * r);
        atomicAdd(&item_s[base0 + 1], A0.y * r);
        atomicAdd(&item_s[base0 + 2], A0.z * r);
        atomicAdd(&item_s[base0 + 3], A0.w * r);
        atomicAdd(&item_s[base1 + 0], A1.x * r);
        atomicAdd(&item_s[base1 + 1], A1.y * r);
        atomicAdd(&item_s[base1 + 2], A1.z * r);
        atomicAdd(&item_s[base1 + 3], A1.w * r);
    }

    // ---- counterfactual softmaxes: warp handles agents i = warp, warp+8 ----
    for (int i = warp; i < NA; i += 8) {
        float mx = -3.4e38f;
        for (int kk = lane; kk < KTOT; kk += 32) {
            float l = (tw_s[kk] - paw_s[kk * PAWS + i] + bp_s[kk]) * temp;
            mx = fmaxf(mx, l);
        }
        #pragma unroll
        for (int o = 16; o; o >>= 1) mx = fmaxf(mx, __shfl_xor_sync(0xffffffffu, mx, o));
        float s0 = 0.f, s1 = 0.f, s2 = 0.f;
        for (int kk = lane; kk < KTOT; kk += 32) {
            float trm = tw_s[kk] - paw_s[kk * PAWS + i];
            float bp  = bp_s[kk];
            float e   = __expf((trm + bp) * temp - mx);
            s0 += e; s1 += e * trm; s2 += e * bp;
        }
        #pragma unroll
        for (int o = 16; o; o >>= 1) {
            s0 += __shfl_xor_sync(0xffffffffu, s0, o);
            s1 += __shfl_xor_sync(0xffffffffu, s1, o);
            s2 += __shfl_xor_sync(0xffffffffu, s2, o);
        }
        if (lane == 0) { rcs_s[i] = s1 / s0; rb_s[i] = s2 / s0; }
    }
    __syncthreads();   // item_s atomics + rcs/rb ready

    // ---- item_allocation out + payments / utility / bid_rev ----
    out[OFF_ITEM + (size_t)b * NM + tid] = item_s[tid];
    if (tid < NA) {
        float br = 0.f, val = 0.f;
        size_t base = (size_t)b * NM + (size_t)tid * MI;
        #pragma unroll
        for (int m = 0; m < MI; ++m) {
            float it = item_s[tid * MI + m];
            br  += it * bids[base + m];
            val += it * values[base + m];
        }
        float pay = (bc_s[1] + bc_s[2] - rcs_s[tid] - rb_s[tid]) / w_s[tid] + br;
        out[OFF_UTIL + (size_t)tid * BBATCH + b] = val - pay;
        out[OFF_PAY  + (size_t)tid * BBATCH + b] = pay;
        out[OFF_BREV + (size_t)tid * BBATCH + b] = br;
    }
}

extern "C" void kernel_launch(void* const* d_in, const int* in_sizes, int n_in,
                              void* d_out, int out_size)
{
    const float* bids   = (const float*)d_in[0];
    const float* values = (const float*)d_in[1];
    const float* allocs = (const float*)d_in[2];
    const float* w      = (const float*)d_in[3];
    const float* b      = (const float*)d_in[4];
    const int*   temp   = (const int*)  d_in[5];
    float* out = (float*)d_out;

    ramanet_kernel<<<BBATCH, 256>>>(bids, values, allocs, w, b, temp, out);
}

// round 14
// speedup vs baseline: 1.0693x; 1.0027x over previous
#include <cuda_runtime.h>
#include <cfloat>

// Problem constants
#define BBATCH 1024
#define NA     16     // agents n
#define MI     16     // items m
#define MENU   256
#define KTOT   257    // MENU + null option
#define NM     256    // NA*MI
#define NM4    64     // NM/4
#define PAWS   17     // padded row stride for per-agent-welfare

// Output layout: concatenation of the reference's 6 returned arrays (all f32)
#define OFF_CHOICE 0                                    // [B,KTOT]
#define OFF_ITEM   (OFF_CHOICE + (size_t)BBATCH*KTOT)   // [B,NA,MI]
#define OFF_UTIL   (OFF_ITEM   + (size_t)BBATCH*NM)     // [NA,B]
#define OFF_PAY    (OFF_UTIL   + (size_t)NA*BBATCH)     // [NA,B]
#define OFF_ALLOCP (OFF_PAY    + (size_t)NA*BBATCH)     // [B,KTOT,NA,MI]
#define OFF_BREV   (OFF_ALLOCP + (size_t)BBATCH*KTOT*NM)// [NA,B]

__device__ __forceinline__ float dot4(float4 a, float4 b) {
    return a.x * b.x + a.y * b.y + a.z * b.z + a.w * b.w;
}

__global__ __launch_bounds__(256, 4)
void ramanet_kernel(const float* __restrict__ bids,
                    const float* __restrict__ values,
                    const float* __restrict__ allocs,
                    const float* __restrict__ wv,
                    const float* __restrict__ bv,
                    const int*   __restrict__ temp_ptr,
                    float* __restrict__ out)
{
    const int b    = blockIdx.x;
    const int tid  = threadIdx.x;
    const int warp = tid >> 5;
    const int lane = tid & 31;

    // decode softmax_temp robustly (int32 500 or float32 500.0f bit pattern)
    int ti = *temp_ptr;
    const float temp = (ti >= 1 && ti <= 10000000) ? (float)ti : __int_as_float(ti);

    __shared__ float4 wvb4_s[NM4];           // w[n] * (value - bid), as float4
    __shared__ float  w_s[NA];
    __shared__ float  bp_s[KTOT];
    __shared__ float  paw_s[KTOT * PAWS];
    __shared__ float  tw_s[KTOT];
    __shared__ float  choice_s[KTOT];
    __shared__ float  item_s[NM];
    __shared__ float  red_s[8];
    __shared__ float  red3_s[24];
    __shared__ float  bc_s[4];               // invSum, chosen_sum, alloc_b, maxv
    __shared__ float  rcs_s[NA], rb_s[NA];

    const float4* abase4 = (const float4*)(allocs + (size_t)b * MENU * NM);
    float4*       outP4  = (float4*)(out + OFF_ALLOCP + (size_t)b * KTOT * NM);

    // null allocation row = zeros (64 float4) — issued early, off the tail
    if (tid < 64)
        __stcs(&((float4*)((float*)outP4 + (size_t)MENU * NM))[tid],
               make_float4(0.f, 0.f, 0.f, 0.f));

    // ---- stage small per-batch data ----
    {
        size_t base = (size_t)b * NM;
        if (tid < NA) w_s[tid] = wv[(size_t)b * NA + tid];
        item_s[tid] = 0.f;
        bp_s[tid]   = bv[(size_t)b * MENU + tid];
        if (tid == 0) bp_s[MENU] = 0.f;
        __syncthreads();   // w_s ready before folding into wvb
        float vb = values[base + tid] - bids[base + tid];
        ((float*)wvb4_s)[tid] = vb * w_s[tid >> 4];   // fold w[n] in (n = tid/16)
    }
    __syncthreads();

    // ---- SINGLE PASS over allocs (x2 per warp): copy-out + per_agent_welfare
    //      + total_welfare + online-softmax accumulation of item_allocation ----
    float  Mw = -FLT_MAX;                         // per-warp running max
    float4 A0 = make_float4(0.f, 0.f, 0.f, 0.f);  // Σ e^{l-Mw} * allocs
    float4 A1 = make_float4(0.f, 0.f, 0.f, 0.f);

    const float4 wvb0 = wvb4_s[lane];             // agent n = lane/4
    const float4 wvb1 = wvb4_s[32 + lane];        // agent n = 8 + lane/4

    for (int k = warp; k < MENU; k += 16) {
        const float4* pa = abase4 + (size_t)k * NM4;
        const float4* pb = pa + 8 * NM4;
        float4 va0 = __ldcs(&pa[lane]);
        float4 va1 = __ldcs(&pa[32 + lane]);
        float4 vc0 = __ldcs(&pb[lane]);
        float4 vc1 = __ldcs(&pb[32 + lane]);
        float4* qa = outP4 + (size_t)k * NM4;
        float4* qb = qa + 8 * NM4;
        __stcs(&qa[lane],      va0);
        __stcs(&qa[32 + lane], va1);
        __stcs(&qb[lane],      vc0);
        __stcs(&qb[32 + lane], vc1);

        float ta0 = dot4(va0, wvb0);
        float ta1 = dot4(va1, wvb1);
        float tb0 = dot4(vc0, wvb0);
        float tb1 = dot4(vc1, wvb1);
        ta0 += __shfl_xor_sync(0xffffffffu, ta0, 2);
        ta1 += __shfl_xor_sync(0xffffffffu, ta1, 2);
        tb0 += __shfl_xor_sync(0xffffffffu, tb0, 2);
        tb1 += __shfl_xor_sync(0xffffffffu, tb1, 2);
        ta0 += __shfl_xor_sync(0xffffffffu, ta0, 1);
        ta1 += __shfl_xor_sync(0xffffffffu, ta1, 1);
        tb0 += __shfl_xor_sync(0xffffffffu, tb0, 1);
        tb1 += __shfl_xor_sync(0xffffffffu, tb1, 1);
        if ((lane & 3) == 0) {
            int n0 = lane >> 2;
            paw_s[k * PAWS + n0]            = ta0;
            paw_s[k * PAWS + 8 + n0]        = ta1;
            paw_s[(k + 8) * PAWS + n0]      = tb0;
            paw_s[(k + 8) * PAWS + 8 + n0]  = tb1;
        }
        float sa = ta0 + ta1;
        float sb = tb0 + tb1;
        sa += __shfl_xor_sync(0xffffffffu, sa, 4);
        sb += __shfl_xor_sync(0xffffffffu, sb, 4);
        sa += __shfl_xor_sync(0xffffffffu, sa, 8);
        sb += __shfl_xor_sync(0xffffffffu, sb, 8);
        sa += __shfl_xor_sync(0xffffffffu, sa, 16);
        sb += __shfl_xor_sync(0xffffffffu, sb, 16);
        if (lane == 0) { tw_s[k] = sa; tw_s[k + 8] = sb; }

        float la = (sa + bp_s[k]) * temp;
        float lb = (sb + bp_s[k + 8]) * temp;
        float Mn = fmaxf(Mw, fmaxf(la, lb));
        float sc = __expf(Mw - Mn);
        float ca = __expf(la - Mn);
        float cb = __expf(lb - Mn);
        Mw = Mn;
        A0.x = A0.x * sc + ca * va0.x + cb * vc0.x;
        A0.y = A0.y * sc + ca * va0.y + cb * vc0.y;
        A0.z = A0.z * sc + ca * va0.z + cb * vc0.z;
        A0.w = A0.w * sc + ca * va0.w + cb * vc0.w;
        A1.x = A1.x * sc + ca * va1.x + cb * vc1.x;
        A1.y = A1.y * sc + ca * va1.y + cb * vc1.y;
        A1.z = A1.z * sc + ca * va1.z + cb * vc1.z;
        A1.w = A1.w * sc + ca * va1.w + cb * vc1.w;
    }

    if (tid < NA) paw_s[MENU * PAWS + tid] = 0.f;   // null option
    if (tid == 0) tw_s[MENU] = 0.f;
    __syncthreads();

    // ---- main softmax over K=257 logits = (tw + bp)*temp ----
    float l0 = (tw_s[tid] + bp_s[tid]) * temp;       // k = tid
    {
        float mx = l0;
        if (tid == 0) mx = fmaxf(mx, 0.f);           // k=256 null logit = 0
        #pragma unroll
        for (int o = 16; o; o >>= 1) mx = fmaxf(mx, __shfl_xor_sync(0xffffffffu, mx, o));
        if (lane == 0) red_s[warp] = mx;
        __syncthreads();
        if (warp == 0) {
            float v = (lane < 8) ? red_s[lane] : -3.4e38f;
            #pragma unroll
            for (int o = 4; o; o >>= 1) v = fmaxf(v, __shfl_xor_sync(0xffffffffu, v, o));
            if (lane == 0) bc_s[3] = v;
        }
        __syncthreads();
    }
    const float maxv = bc_s[3];
    float e0 = __expf(l0 - maxv);
    choice_s[tid] = e0;
    float eNull = 0.f;
    if (tid == 0) { eNull = __expf(0.f - maxv); choice_s[MENU] = eNull; }

    // triple block sum: (Σe, Σe*tw, Σe*bp)
    {
        float s0 = e0 + eNull;                       // null adds e; its tw=bp=0
        float s1 = e0 * tw_s[tid];
        float s2 = e0 * bp_s[tid];
        #pragma unroll
        for (int o = 16; o; o >>= 1) {
            s0 += __shfl_xor_sync(0xffffffffu, s0, o);
            s1 += __shfl_xor_sync(0xffffffffu, s1, o);
            s2 += __shfl_xor_sync(0xffffffffu, s2, o);
        }
        if (lane == 0) { red3_s[warp] = s0; red3_s[8+warp] = s1; red3_s[16+warp] = s2; }
        __syncthreads();
        if (warp == 0) {
            float a = (lane < 8) ? red3_s[lane]     : 0.f;
            float c = (lane < 8) ? red3_s[8+lane]   : 0.f;
            float d = (lane < 8) ? red3_s[16+lane]  : 0.f;
            #pragma unroll
            for (int o = 4; o; o >>= 1) {
                a += __shfl_xor_sync(0xffffffffu, a, o);
                c += __shfl_xor_sync(0xffffffffu, c, o);
                d += __shfl_xor_sync(0xffffffffu, d, o);
            }
            if (lane == 0) {
                float inv = 1.f / a;
                bc_s[0] = inv;
                bc_s[1] = c * inv;   // chosen_sum
                bc_s[2] = d * inv;   // alloc_b
            }
        }
        __syncthreads();
    }
    const float invSum = bc_s[0];
    // write alloc_choice
    out[OFF_CHOICE + (size_t)b * KTOT + tid] = choice_s[tid] * invSum;
    if (tid == 0)
        out[OFF_CHOICE + (size_t)b * KTOT + MENU] = choice_s[MENU] * invSum;

    // ---- merge per-warp online accumulators into item_allocation ----
    {
        float r = __expf(Mw - maxv) * invSum;        // lane-uniform per warp
        int base0 = lane * 4, base1 = (32 + lane) * 4;
        atomicAdd(&item_s[base0 + 0], A0.x * r);
        atomicAdd(&item_s[base0 + 1], A0.y * r);
        atomicAdd(&item_s[base0 + 2], A0.z * r);
        atomicAdd(&item_s[base0 + 3], A0.w * r);
        atomicAdd(&item_s[base1 + 0], A1.x * r);
        atomicAdd(&item_s[base1 + 1], A1.y * r);
        atomicAdd(&item_s[base1 + 2], A1.z * r);
        atomicAdd(&item_s[base1 + 3], A1.w * r);
    }

    // ---- counterfactual softmaxes: warp handles agents i = warp, warp+8 ----
    for (int i = warp; i < NA; i += 8) {
        float mx = -3.4e38f;
        for (int kk = lane; kk < KTOT; kk += 32) {
            float l = (tw_s[kk] - paw_s[kk * PAWS + i] + bp_s[kk]) * temp;
            mx = fmaxf(mx, l);
        }
        #pragma unroll
        for (int o = 16; o; o >>= 1) mx = fmaxf(mx, __shfl_xor_sync(0xffffffffu, mx, o));
        float s0 = 0.f, s1 = 0.f, s2 = 0.f;
        for (int kk = lane; kk < KTOT; kk += 32) {
            float trm = tw_s[kk] - paw_s[kk * PAWS + i];
            float bp  = bp_s[kk];
            float e   = __expf((trm + bp) * temp - mx);
            s0 += e; s1 += e * trm; s2 += e * bp;
        }
        #pragma unroll
        for (int o = 16; o; o >>= 1) {
            s0 += __shfl_xor_sync(0xffffffffu, s0, o);
            s1 += __shfl_xor_sync(0xffffffffu, s1, o);
            s2 += __shfl_xor_sync(0xffffffffu, s2, o);
        }
        if (lane == 0) { rcs_s[i] = s1 / s0; rb_s[i] = s2 / s0; }
    }
    __syncthreads();   // item_s atomics + rcs/rb ready

    // ---- item_allocation out + payments / utility / bid_rev ----
    out[OFF_ITEM + (size_t)b * NM + tid] = item_s[tid];
    if (tid < NA) {
        float br = 0.f, val = 0.f;
        size_t base = (size_t)b * NM + (size_t)tid * MI;
        #pragma unroll
        for (int m = 0; m < MI; ++m) {
            float it = item_s[tid * MI + m];
            br  += it * bids[base + m];
            val += it * values[base + m];
        }
        float pay = (bc_s[1] + bc_s[2] - rcs_s[tid] - rb_s[tid]) / w_s[tid] + br;
        out[OFF_UTIL + (size_t)tid * BBATCH + b] = val - pay;
        out[OFF_PAY  + (size_t)tid * BBATCH + b] = pay;
        out[OFF_BREV + (size_t)tid * BBATCH + b] = br;
    }
}

extern "C" void kernel_launch(void* const* d_in, const int* in_sizes, int n_in,
                              void* d_out, int out_size)
{
    const float* bids   = (const float*)d_in[0];
    const float* values = (const float*)d_in[1];
    const float* allocs = (const float*)d_in[2];
    const float* w      = (const float*)d_in[3];
    const float* b      = (const float*)d_in[4];
    const int*   temp   = (const int*)  d_in[5];
    float* out = (float*)d_out;

    ramanet_kernel<<<BBATCH, 256>>>(bids, values, allocs, w, b, temp, out);
}